// round 10
// baseline (speedup 1.0000x reference)
#include <cuda_runtime.h>
#include <cstdint>

// CARAFE: N=4, C=256, H=W=64, K=5, G=1, S=2  ->  out [4,256,128,128] f32
#define KK   5
#define N_   4
#define C_   256
#define H_   64
#define W_   64
#define HO   128
#define WO   128

#define TC   4              // cells per tile (both dims)
#define PR   8              // patch rows = TC + 4
#define PCC  8              // patch cols = TC + 4
#define RS4  9              // patch row stride in float4 units (odd stagger)
#define QUADF (PR * RS4 * 4)     // 288 floats per 4-channel quad patch
#define STAGE_F (2 * QUADF)      // 576 floats per 8-channel stage
#define NTHREADS 128
#define NSTAGE 32                // all 256 channels: masks loaded once
#define NLOAD (8 * PR * PCC)     // 512 feature elements per stage
#define LPT (NLOAD / NTHREADS)   // 4

typedef unsigned long long ull;

__device__ __forceinline__ ull pack2(float lo, float hi) {
    ull r;
    asm("mov.b64 %0, {%1, %2};" : "=l"(r) : "f"(lo), "f"(hi));
    return r;
}
__device__ __forceinline__ void unpack2(float& lo, float& hi, ull v) {
    asm("mov.b64 {%0, %1}, %2;" : "=f"(lo), "=f"(hi) : "l"(v));
}
__device__ __forceinline__ void ffma2(ull& d, ull a, ull b) {
    asm("fma.rn.f32x2 %0, %1, %2, %0;" : "+l"(d) : "l"(a), "l"(b));
}

__global__ void __launch_bounds__(NTHREADS, 5)
carafe_kernel(const float* __restrict__ feat, const float* __restrict__ masks,
              float* __restrict__ out)
{
    __shared__ __align__(16) float sbuf[2][STAGE_F];   // 2*576*4 = 4608 B

    const int t    = threadIdx.x;
    const int slot = t >> 6;          // 0/1 : 4-channel quad (uniform per warp)
    const int r6   = t & 63;
    const int cell = r6 >> 2;         // 0..15 : cell in 4x4 tile
    const int pq   = t & 3;
    const int p    = pq >> 1;         // output sub-row
    const int qx   = pq & 1;          // output sub-col
    const int hh   = cell >> 2;       // 0..3
    const int ww   = cell & 3;        // 0..3

    const int b    = blockIdx.x;      // 0..1023
    const int n    = b >> 8;
    const int tile = b & 255;
    const int tr   = tile >> 4;       // 0..15
    const int tc   = tile & 15;       // 0..15
    const int h0   = tr * TC;
    const int w0   = tc * TC;
    const int oh   = (h0 + hh) * 2 + p;
    const int ow   = (w0 + ww) * 2 + qx;

    // ---- per-thread masks: 25 taps, pre-duplicated for channel-packed FFMA2 ----
    ull m[25];
    {
        const float* mb = masks + (size_t)n * 25 * (HO * WO) + (size_t)oh * WO + ow;
        #pragma unroll
        for (int k = 0; k < 25; ++k) {
            const float mv = __ldg(mb + (size_t)k * (HO * WO));
            m[k] = pack2(mv, mv);
        }
    }

    // ---- cooperative-load slots: float4 quad layout ----
    const float* fbase = feat + (size_t)n * (C_ * H_ * W_);
    int sofs[LPT], gofs[LPT];
    #pragma unroll
    for (int i = 0; i < LPT; ++i) {
        const int e   = t + i * NTHREADS;          // < 512
        const int ch  = e >> 6;                    // 0..7
        const int rem = e & 63;
        const int rr  = rem >> 3;                  // patch row 0..7
        const int col = rem & 7;                   // patch col 0..7
        const int gr  = h0 - 2 + rr;
        const int gc  = w0 - 2 + col;
        sofs[i] = (ch >> 2) * QUADF + (rr * RS4 + col) * 4 + (ch & 3);
        gofs[i] = ((unsigned)gr < (unsigned)H_ && (unsigned)gc < (unsigned)W_)
                      ? (ch * (H_ * W_) + gr * W_ + gc)
                      : -1;
    }

    float v[LPT];

    // prologue: stage 0 -> buffer 0
    #pragma unroll
    for (int i = 0; i < LPT; ++i)
        v[i] = (gofs[i] >= 0) ? __ldg(fbase + gofs[i]) : 0.f;
    #pragma unroll
    for (int i = 0; i < LPT; ++i)
        sbuf[0][sofs[i]] = v[i];
    __syncthreads();

    float* obase = out + (size_t)n * (C_ * HO * WO) + (size_t)oh * WO + ow;

    #pragma unroll 1
    for (int s = 0; s < NSTAGE; ++s) {
        // prefetch next stage's features (latency hidden under compute)
        if (s + 1 < NSTAGE) {
            const float* fb = fbase + (size_t)(s + 1) * 8 * (H_ * W_);
            #pragma unroll
            for (int i = 0; i < LPT; ++i)
                v[i] = (gofs[i] >= 0) ? __ldg(fb + gofs[i]) : 0.f;
        }

        // compute: 25 taps, each = 1 LDS.128 (4 channels) + 2 FFMA2
        const float* sb = &sbuf[s & 1][0] + slot * QUADF + (hh * RS4 + ww) * 4;
        ull a01 = 0, a23 = 0;
        #pragma unroll
        for (int ki = 0; ki < KK; ++ki) {
            #pragma unroll
            for (int kj = 0; kj < KK; ++kj) {
                const int k = ki * KK + kj;
                const float4 f = *(const float4*)(sb + (ki * RS4 + kj) * 4);
                ffma2(a01, pack2(f.x, f.y), m[k]);
                ffma2(a23, pack2(f.z, f.w), m[k]);
            }
        }

        // stores: 4 channels, channel-strided STG.32 (32B-sector aligned per row-group)
        {
            const int c0 = s * 8 + slot * 4;
            float x, y;
            unpack2(x, y, a01);
            obase[(size_t)(c0 + 0) * (HO * WO)] = x;
            obase[(size_t)(c0 + 1) * (HO * WO)] = y;
            unpack2(x, y, a23);
            obase[(size_t)(c0 + 2) * (HO * WO)] = x;
            obase[(size_t)(c0 + 3) * (HO * WO)] = y;
        }

        // commit prefetched data to the other buffer
        if (s + 1 < NSTAGE) {
            float* dst = &sbuf[(s + 1) & 1][0];
            #pragma unroll
            for (int i = 0; i < LPT; ++i)
                dst[sofs[i]] = v[i];
        }
        __syncthreads();
    }
}

extern "C" void kernel_launch(void* const* d_in, const int* in_sizes, int n_in,
                              void* d_out, int out_size) {
    const float* feat  = (const float*)d_in[0];
    const float* masks = (const float*)d_in[1];
    if (n_in >= 2 && in_sizes[0] == N_ * KK * KK * HO * WO &&
        in_sizes[1] == N_ * C_ * H_ * W_) {
        const float* tmp = feat; feat = masks; masks = tmp;
    }
    carafe_kernel<<<N_ * 256, NTHREADS>>>(feat, masks, (float*)d_out);
}

// round 11
// speedup vs baseline: 1.3250x; 1.3250x over previous
#include <cuda_runtime.h>
#include <cstdint>

// CARAFE: N=4, C=256, H=W=64, K=5, G=1, S=2  ->  out [4,256,128,128] f32
#define KK   5
#define N_   4
#define C_   256
#define H_   64
#define W_   64
#define HO   128
#define WO   128

#define TH_CELLS 4         // input cells per CTA (rows)
#define TW_CELLS 8         // input cells per CTA (cols)
#define PR 8               // patch rows = TH_CELLS + 4
#define PC 12              // patch cols = TW_CELLS + 4
#define PS 13              // row stride in float2 units (odd stagger)
#define PAIR_F (PR * PS * 2)      // 208 floats per channel-pair patch
#define STAGE_F (4 * PAIR_F)      // 832 floats per 8-channel stage
#define NTHREADS 128
#define NCHUNK 2                  // channel split: 2 CTAs per tile
#define CHPC (C_ / NCHUNK)        // 128 channels per CTA
#define NSTAGE (CHPC / 8)         // 16 stages of 8 channels
#define NLOAD (8 * PR * PC)       // 768 feature elements per stage
#define LPT (NLOAD / NTHREADS)    // 6

typedef unsigned long long ull;

__device__ __forceinline__ ull pack2(float lo, float hi) {
    ull r;
    asm("mov.b64 %0, {%1, %2};" : "=l"(r) : "f"(lo), "f"(hi));
    return r;
}
__device__ __forceinline__ void unpack2(float& lo, float& hi, ull v) {
    asm("mov.b64 {%0, %1}, %2;" : "=f"(lo), "=f"(hi) : "l"(v));
}
__device__ __forceinline__ void ffma2(ull& d, ull a, ull b) {
    asm("fma.rn.f32x2 %0, %1, %2, %0;" : "+l"(d) : "l"(a), "l"(b));
}

__global__ void __launch_bounds__(NTHREADS, 4)
carafe_kernel(const float* __restrict__ feat, const float* __restrict__ masks,
              float* __restrict__ out)
{
    __shared__ __align__(16) float sbuf[2][STAGE_F];   // 6656 B

    const int t    = threadIdx.x;
    const int oh_l = t >> 4;          // 0..7  local output row
    const int ow_l = t & 15;          // 0..15 local output col
    const int hh   = oh_l >> 1;       // input cell row 0..3
    const int wwq  = ow_l >> 1;       // input cell col 0..7

    const int b     = blockIdx.x;     // 0..1023
    const int chunk = b & 1;          // LSB: the 2 CTAs sharing a tile's masks are adjacent
    const int tidx  = (b >> 1) & 127;
    const int n     = b >> 8;
    const int th    = tidx >> 3;      // 0..15
    const int tw    = tidx & 7;       // 0..7
    const int h0    = th * TH_CELLS;
    const int w0    = tw * TW_CELLS;
    const int oh    = th * (2 * TH_CELLS) + oh_l;
    const int ow    = tw * (2 * TW_CELLS) + ow_l;

    // ---- per-thread masks (one output pixel), duplicated for channel-packed FFMA2 ----
    ull m[25];
    {
        const float* mb = masks + (size_t)n * 25 * (HO * WO) + (size_t)oh * WO + ow;
        #pragma unroll
        for (int k = 0; k < 25; ++k) {
            const float mv = __ldg(mb + (size_t)k * (HO * WO));
            m[k] = pack2(mv, mv);
        }
    }

    // ---- cooperative-load slots: interleaved (ch&1) channel-pair layout ----
    const float* fbase = feat + (size_t)n * (C_ * H_ * W_)
                              + (size_t)chunk * CHPC * (H_ * W_);
    int sofs[LPT], gofs[LPT];
    #pragma unroll
    for (int i = 0; i < LPT; ++i) {
        const int e   = t + i * NTHREADS;          // < 768
        const int ch  = e / (PR * PC);
        const int rem = e - ch * (PR * PC);
        const int r   = rem / PC;
        const int col = rem - r * PC;
        const int gr  = h0 - 2 + r;
        const int gc  = w0 - 2 + col;
        sofs[i] = (ch >> 1) * PAIR_F + r * (PS * 2) + col * 2 + (ch & 1);
        gofs[i] = ((unsigned)gr < (unsigned)H_ && (unsigned)gc < (unsigned)W_)
                      ? (ch * (H_ * W_) + gr * W_ + gc)
                      : -1;
    }

    float v[LPT];

    // prologue: stage 0 -> buffer 0
    #pragma unroll
    for (int i = 0; i < LPT; ++i)
        v[i] = (gofs[i] >= 0) ? __ldg(fbase + gofs[i]) : 0.f;
    #pragma unroll
    for (int i = 0; i < LPT; ++i)
        sbuf[0][sofs[i]] = v[i];
    __syncthreads();

    float* obase = out + (size_t)n * (C_ * HO * WO)
                       + (size_t)chunk * CHPC * (HO * WO)
                       + (size_t)oh * WO + ow;

    #pragma unroll 1
    for (int s = 0; s < NSTAGE; ++s) {
        // prefetch next stage's features (latency hidden under compute)
        if (s + 1 < NSTAGE) {
            const float* fb = fbase + (size_t)(s + 1) * 8 * (H_ * W_);
            #pragma unroll
            for (int i = 0; i < LPT; ++i)
                v[i] = (gofs[i] >= 0) ? __ldg(fb + gofs[i]) : 0.f;
        }

        // compute: 4 channel pairs x 25 taps, LDS.64 + FFMA2 each
        const float* sb = &sbuf[s & 1][0] + hh * (PS * 2) + wwq * 2;
        ull a0 = 0, a1 = 0, a2 = 0, a3 = 0;
        #pragma unroll
        for (int ki = 0; ki < KK; ++ki) {
            #pragma unroll
            for (int kj = 0; kj < KK; ++kj) {
                const int k   = ki * KK + kj;
                const int off = ki * (PS * 2) + kj * 2;
                const ull f0 = *(const ull*)(sb + 0 * PAIR_F + off);
                const ull f1 = *(const ull*)(sb + 1 * PAIR_F + off);
                const ull f2 = *(const ull*)(sb + 2 * PAIR_F + off);
                const ull f3 = *(const ull*)(sb + 3 * PAIR_F + off);
                ffma2(a0, f0, m[k]);
                ffma2(a1, f1, m[k]);
                ffma2(a2, f2, m[k]);
                ffma2(a3, f3, m[k]);
            }
        }

        // stores: 8 channels, channel-strided (coalesced across the warp)
        {
            const int c0 = s * 8;
            float lo, hi;
            unpack2(lo, hi, a0);
            obase[(size_t)(c0 + 0) * (HO * WO)] = lo;
            obase[(size_t)(c0 + 1) * (HO * WO)] = hi;
            unpack2(lo, hi, a1);
            obase[(size_t)(c0 + 2) * (HO * WO)] = lo;
            obase[(size_t)(c0 + 3) * (HO * WO)] = hi;
            unpack2(lo, hi, a2);
            obase[(size_t)(c0 + 4) * (HO * WO)] = lo;
            obase[(size_t)(c0 + 5) * (HO * WO)] = hi;
            unpack2(lo, hi, a3);
            obase[(size_t)(c0 + 6) * (HO * WO)] = lo;
            obase[(size_t)(c0 + 7) * (HO * WO)] = hi;
        }

        // commit prefetched data to the other buffer
        if (s + 1 < NSTAGE) {
            float* dst = &sbuf[(s + 1) & 1][0];
            #pragma unroll
            for (int i = 0; i < LPT; ++i)
                dst[sofs[i]] = v[i];
        }
        __syncthreads();
    }
}

extern "C" void kernel_launch(void* const* d_in, const int* in_sizes, int n_in,
                              void* d_out, int out_size) {
    const float* feat  = (const float*)d_in[0];
    const float* masks = (const float*)d_in[1];
    if (n_in >= 2 && in_sizes[0] == N_ * KK * KK * HO * WO &&
        in_sizes[1] == N_ * C_ * H_ * W_) {
        const float* tmp = feat; feat = masks; masks = tmp;
    }
    carafe_kernel<<<N_ * 128 * NCHUNK, NTHREADS>>>(feat, masks, (float*)d_out);
}